// round 3
// baseline (speedup 1.0000x reference)
#include <cuda_runtime.h>
#include <cuda_bf16.h>
#include <cstdint>
#include <cstddef>

#define DI __device__ __forceinline__

// ---------------- problem constants ----------------
constexpr int BATCH = 8, CH = 512, TT = 4096, PAD = 8, TP = TT + 2 * PAD;
constexpr int WELEM = CH * CH * 3;        // weights per conv
constexpr int WROW  = 3 * CH;             // 1536 (K per output row)
constexpr int TILE  = 128;                // M and N tile
constexpr int KC    = 64;                 // K chunk (bf16 elems)
constexpr int NCHK  = 24;                 // 3 taps * (512/64)
// dynamic SMEM: A | B-hi | B-lo, each double-buffered 2x16KB
constexpr int A_OFF  = 0;
constexpr int BH_OFF = 32768;
constexpr int BL_OFF = 65536;
constexpr int SMEM_SZ = 98304;

// ---------------- static device scratch ----------------
__device__ __align__(256) float         g_r[(size_t)BATCH * TT * CH];
__device__ __align__(256) __nv_bfloat16 g_xhi[(size_t)BATCH * TP * CH];
__device__ __align__(256) __nv_bfloat16 g_xlo[(size_t)BATCH * TP * CH];
__device__ __align__(256) __nv_bfloat16 g_hhi[(size_t)BATCH * TP * CH];
__device__ __align__(256) __nv_bfloat16 g_hlo[(size_t)BATCH * TP * CH];
__device__ __align__(256) __nv_bfloat16 g_wq[6][(size_t)CH * WROW];
__device__ float  g_s[6];
__device__ double g_part[6 * 64];
__device__ float  g_a[3 * CH];
__device__ float  g_binv[3 * CH];

// ---------------- PTX helpers (sm_80-class only; no 'a' features) ----------------
DI uint32_t smem_u32(const void* p) {
    uint32_t a;
    asm("{ .reg .u64 t; cvta.to.shared.u64 t, %1; cvt.u32.u64 %0, t; }" : "=r"(a) : "l"(p));
    return a;
}
DI uint32_t swz(uint32_t o) { return o ^ ((o >> 3) & 0x70); }

DI void cp16(uint32_t dst, const void* src) {
    asm volatile("cp.async.cg.shared.global [%0], [%1], 16;" :: "r"(dst), "l"(src) : "memory");
}
DI void cp_commit() { asm volatile("cp.async.commit_group;" ::: "memory"); }
template <int N> DI void cp_wait() { asm volatile("cp.async.wait_group %0;" :: "n"(N) : "memory"); }

DI void ldm4(uint32_t* r, uint32_t addr) {
    asm volatile("ldmatrix.sync.aligned.m8n8.x4.shared.b16 {%0,%1,%2,%3}, [%4];"
                 : "=r"(r[0]), "=r"(r[1]), "=r"(r[2]), "=r"(r[3]) : "r"(addr));
}
DI void mma16816(float* c, const uint32_t* a, const uint32_t* b) {
    asm volatile(
        "mma.sync.aligned.m16n8k16.row.col.f32.bf16.bf16.f32 "
        "{%0,%1,%2,%3}, {%4,%5,%6,%7}, {%8,%9}, {%0,%1,%2,%3};"
        : "+f"(c[0]), "+f"(c[1]), "+f"(c[2]), "+f"(c[3])
        : "r"(a[0]), "r"(a[1]), "r"(a[2]), "r"(a[3]), "r"(b[0]), "r"(b[1]));
}

// ---------------- prep kernels ----------------
__global__ void k_wabs(const float* __restrict__ w1, const float* __restrict__ w2) {
    int conv = blockIdx.x >> 6, part = blockIdx.x & 63;
    const float* w = ((conv & 1) ? w2 : w1) + (size_t)(conv >> 1) * WELEM;
    int base = part * (WELEM / 64);
    double acc = 0.0;
    for (int i = threadIdx.x; i < WELEM / 64; i += 256) acc += (double)fabsf(w[base + i]);
    __shared__ double sm[256];
    sm[threadIdx.x] = acc;
    __syncthreads();
    for (int s = 128; s > 0; s >>= 1) {
        if (threadIdx.x < s) sm[threadIdx.x] += sm[threadIdx.x + s];
        __syncthreads();
    }
    if (threadIdx.x == 0) g_part[blockIdx.x] = sm[0];
}

__global__ void k_sfin() {
    __shared__ double sm[64];
    sm[threadIdx.x] = g_part[blockIdx.x * 64 + threadIdx.x];
    __syncthreads();
    for (int s = 32; s > 0; s >>= 1) {
        if (threadIdx.x < s) sm[threadIdx.x] += sm[threadIdx.x + s];
        __syncthreads();
    }
    if (threadIdx.x == 0) g_s[blockIdx.x] = (float)(sm[0] / (double)WELEM);
}

__global__ void k_quant(const float* __restrict__ w1, const float* __restrict__ w2) {
    size_t idx = (size_t)blockIdx.x * 256 + threadIdx.x;
    if (idx >= (size_t)6 * WELEM) return;
    int conv = (int)(idx / WELEM);
    int e = (int)(idx - (size_t)conv * WELEM);
    int co = e / WROW;
    int rem = e - co * WROW;
    int k = rem >> 9, ci = rem & 511;                 // dst layout [co][tap][ci]
    const float* w = ((conv & 1) ? w2 : w1) + (size_t)(conv >> 1) * WELEM;
    float s = g_s[conv] + 1e-5f;
    float q = rintf(w[(size_t)co * WROW + ci * 3 + k] / s); // src layout [co][ci][k]
    q = fminf(1.f, fmaxf(-1.f, q));
    g_wq[conv][e] = __float2bfloat16(q);
}

__global__ void k_act(const float* __restrict__ alpha, const float* __restrict__ beta) {
    int i = blockIdx.x * 256 + threadIdx.x;
    if (i >= 3 * CH) return;
    g_a[i] = expf(alpha[i]);
    g_binv[i] = 1.f / (expf(beta[i]) + 1e-9f);
}

__global__ void k_prep(const float* __restrict__ x) {
    __shared__ float tile[32][33];
    int b = blockIdx.z, c0 = blockIdx.y * 32, t0 = blockIdx.x * 32;
    int tx = threadIdx.x;
    for (int i = threadIdx.y; i < 32; i += 8)
        tile[i][tx] = x[((size_t)b * CH + c0 + i) * TT + t0 + tx];
    __syncthreads();
    for (int i = threadIdx.y; i < 32; i += 8) {
        float v = tile[tx][i];   // channel c0+tx, token t0+i
        size_t ro = ((size_t)b * TT + t0 + i) * CH + c0 + tx;
        size_t po = ((size_t)b * TP + PAD + t0 + i) * CH + c0 + tx;
        g_r[ro] = v;
        __nv_bfloat16 hi = __float2bfloat16(v);
        g_xhi[po] = hi;
        g_xlo[po] = __float2bfloat16(v - __bfloat162float(hi));
    }
}

__global__ void k_out(float* __restrict__ out) {
    __shared__ float tile[32][33];
    int b = blockIdx.z, c0 = blockIdx.y * 32, t0 = blockIdx.x * 32;
    int tx = threadIdx.x;
    for (int i = threadIdx.y; i < 32; i += 8)
        tile[i][tx] = g_r[((size_t)b * TT + t0 + i) * CH + c0 + tx];
    __syncthreads();
    for (int i = threadIdx.y; i < 32; i += 8)
        out[((size_t)b * CH + c0 + i) * TT + t0 + tx] = tile[tx][i];
}

// ---------------- GEMM chunk loader (256 threads) ----------------
DI void load_chunk(int c, int tid, uint32_t sb, int m0, int b, int t0, int dil,
                   const __nv_bfloat16* __restrict__ Xhi,
                   const __nv_bfloat16* __restrict__ Xlo,
                   const __nv_bfloat16* __restrict__ W) {
    int buf = c & 1, tap = c >> 3, ci0 = (c & 7) * KC;
    int shift = (tap - 1) * dil;
    const __nv_bfloat16* As = W + (size_t)m0 * WROW + tap * CH + ci0;
    size_t brow = ((size_t)b * TP + PAD + t0 + shift) * CH + ci0;
    uint32_t ab = sb + A_OFF + buf * 16384;
    uint32_t hb = sb + BH_OFF + buf * 16384;
    uint32_t lb = sb + BL_OFF + buf * 16384;
#pragma unroll
    for (int j = 0; j < 4; j++) {
        int idx = tid + 256 * j;          // 0..1023
        int row = idx >> 3, c16 = idx & 7;
        uint32_t so = swz((uint32_t)(row * 128 + c16 * 16));
        cp16(ab + so, (const char*)(As + (size_t)row * WROW) + c16 * 16);
        cp16(hb + so, (const char*)(Xhi + brow + (size_t)row * CH) + c16 * 16);
        cp16(lb + so, (const char*)(Xlo + brow + (size_t)row * CH) + c16 * 16);
    }
    cp_commit();
}

// ---------------- main GEMM kernel ----------------
// MODE 0: conv1 -> snake -> write g_h hi/lo
// MODE 1: conv2 -> residual update g_r, write g_x hi/lo for next block
// MODE 2: conv2 final -> residual update g_r only
template <int DIL, int MODE>
__global__ void __launch_bounds__(256, 1)
gemm_k(int conv, const float* __restrict__ bias) {
    extern __shared__ char smem[];
    uint32_t sb = smem_u32(smem);
    int tid = threadIdx.x;
    int wid = tid >> 5, lane = tid & 31;
    int wm = wid >> 2, wn = wid & 3;       // warp grid 2m x 4n (64x32 per warp)
    int m0 = blockIdx.x * TILE;
    int nt = blockIdx.y;
    int b = nt >> 5, t0 = (nt & 31) * TILE;
    const __nv_bfloat16* Xhi = (MODE == 0) ? g_xhi : g_hhi;
    const __nv_bfloat16* Xlo = (MODE == 0) ? g_xlo : g_hlo;
    const __nv_bfloat16* W = g_wq[conv];

    float acc[4][4][4];
#pragma unroll
    for (int i = 0; i < 4; i++)
#pragma unroll
        for (int j = 0; j < 4; j++)
#pragma unroll
            for (int r = 0; r < 4; r++) acc[i][j][r] = 0.f;

    // ldmatrix lane roles
    int lsel = lane >> 3, l7 = lane & 7;
    int a_row = (lsel & 1) * 8 + l7, a_kc = (lsel >> 1) * 8;   // A: m8 pair, k8 pair
    int b_row = (lsel >> 1) * 8 + l7, b_kc = (lsel & 1) * 8;   // B: n8 pair, k8 pair

    load_chunk(0, tid, sb, m0, b, t0, DIL, Xhi, Xlo, W);
    for (int c = 0; c < NCHK; c++) {
        if (c + 1 < NCHK) {
            load_chunk(c + 1, tid, sb, m0, b, t0, DIL, Xhi, Xlo, W);
            cp_wait<1>();
        } else {
            cp_wait<0>();
        }
        __syncthreads();
        int buf = c & 1;
        uint32_t ab = sb + A_OFF + buf * 16384;
        uint32_t hb = sb + BH_OFF + buf * 16384;
        uint32_t lb = sb + BL_OFF + buf * 16384;
#pragma unroll
        for (int ks = 0; ks < 4; ks++) {
            uint32_t afr[4][4];
#pragma unroll
            for (int mf = 0; mf < 4; mf++) {
                uint32_t o = (uint32_t)((wm * 64 + mf * 16 + a_row) * 128 + (ks * 16 + a_kc) * 2);
                ldm4(afr[mf], ab + swz(o));
            }
            uint32_t bh[4][2], bl[4][2];
#pragma unroll
            for (int h = 0; h < 2; h++) {
                uint32_t o = (uint32_t)((wn * 32 + h * 16 + b_row) * 128 + (ks * 16 + b_kc) * 2);
                uint32_t r4[4];
                ldm4(r4, hb + swz(o));
                bh[2 * h][0] = r4[0]; bh[2 * h][1] = r4[1];
                bh[2 * h + 1][0] = r4[2]; bh[2 * h + 1][1] = r4[3];
                ldm4(r4, lb + swz(o));
                bl[2 * h][0] = r4[0]; bl[2 * h][1] = r4[1];
                bl[2 * h + 1][0] = r4[2]; bl[2 * h + 1][1] = r4[3];
            }
#pragma unroll
            for (int mf = 0; mf < 4; mf++)
#pragma unroll
                for (int nf = 0; nf < 4; nf++) {
                    mma16816(acc[mf][nf], afr[mf], bh[nf]);
                    mma16816(acc[mf][nf], afr[mf], bl[nf]);
                }
        }
        __syncthreads();
    }

    // -------- epilogue --------
    const float s = g_s[conv];
    const int blkI = conv >> 1;
    int g = lane >> 2, tig = lane & 3;
    float biv[4][2], av[4][2], bvv[4][2];
#pragma unroll
    for (int mf = 0; mf < 4; mf++) {
        int co = m0 + wm * 64 + mf * 16 + g;
        biv[mf][0] = bias[co];
        biv[mf][1] = bias[co + 8];
        if (MODE == 0) {
            av[mf][0] = g_a[blkI * CH + co];
            av[mf][1] = g_a[blkI * CH + co + 8];
            bvv[mf][0] = g_binv[blkI * CH + co];
            bvv[mf][1] = g_binv[blkI * CH + co + 8];
        }
    }
#pragma unroll
    for (int mf = 0; mf < 4; mf++) {
        int co0 = m0 + wm * 64 + mf * 16 + g;
#pragma unroll
        for (int nf = 0; nf < 4; nf++) {
            int tb = t0 + wn * 32 + nf * 8 + 2 * tig;
#pragma unroll
            for (int r = 0; r < 4; r++) {
                int co = co0 + (r >> 1) * 8;
                int t = tb + (r & 1);
                float v = s * acc[mf][nf][r] + biv[mf][r >> 1];
                if (MODE == 0) {
                    float sn = __sinf(av[mf][r >> 1] * v);
                    v += bvv[mf][r >> 1] * sn * sn;
                    size_t o = ((size_t)b * TP + PAD + t) * CH + co;
                    __nv_bfloat16 hi = __float2bfloat16(v);
                    g_hhi[o] = hi;
                    g_hlo[o] = __float2bfloat16(v - __bfloat162float(hi));
                } else {
                    size_t ro = ((size_t)b * TT + t) * CH + co;
                    float rn = g_r[ro] + v;
                    g_r[ro] = rn;
                    if (MODE == 1) {
                        size_t o = ((size_t)b * TP + PAD + t) * CH + co;
                        __nv_bfloat16 hi = __float2bfloat16(rn);
                        g_xhi[o] = hi;
                        g_xlo[o] = __float2bfloat16(rn - __bfloat162float(hi));
                    }
                }
            }
        }
    }
}

// ---------------- launch ----------------
extern "C" void kernel_launch(void* const* d_in, const int* in_sizes, int n_in,
                              void* d_out, int out_size) {
    const float* x     = (const float*)d_in[0];
    const float* w1    = (const float*)d_in[1];
    const float* b1    = (const float*)d_in[2];
    const float* alpha = (const float*)d_in[3];
    const float* beta  = (const float*)d_in[4];
    const float* w2    = (const float*)d_in[5];
    const float* b2    = (const float*)d_in[6];
    float* out = (float*)d_out;

    cudaFuncSetAttribute(gemm_k<1, 0>, cudaFuncAttributeMaxDynamicSharedMemorySize, SMEM_SZ);
    cudaFuncSetAttribute(gemm_k<1, 1>, cudaFuncAttributeMaxDynamicSharedMemorySize, SMEM_SZ);
    cudaFuncSetAttribute(gemm_k<3, 0>, cudaFuncAttributeMaxDynamicSharedMemorySize, SMEM_SZ);
    cudaFuncSetAttribute(gemm_k<5, 0>, cudaFuncAttributeMaxDynamicSharedMemorySize, SMEM_SZ);
    cudaFuncSetAttribute(gemm_k<1, 2>, cudaFuncAttributeMaxDynamicSharedMemorySize, SMEM_SZ);

    k_wabs<<<6 * 64, 256>>>(w1, w2);
    k_sfin<<<6, 64>>>();
    k_quant<<<(int)(((size_t)6 * WELEM + 255) / 256), 256>>>(w1, w2);
    k_act<<<6, 256>>>(alpha, beta);

    dim3 tb(32, 8), tg(TT / 32, CH / 32, BATCH);
    k_prep<<<tg, tb>>>(x);

    dim3 gg(CH / TILE, BATCH * TT / TILE);   // (4, 256)
    gemm_k<1, 0><<<gg, 256, SMEM_SZ>>>(0, b1);
    gemm_k<1, 1><<<gg, 256, SMEM_SZ>>>(1, b2);
    gemm_k<3, 0><<<gg, 256, SMEM_SZ>>>(2, b1 + 512);
    gemm_k<1, 1><<<gg, 256, SMEM_SZ>>>(3, b2 + 512);
    gemm_k<5, 0><<<gg, 256, SMEM_SZ>>>(4, b1 + 1024);
    gemm_k<1, 2><<<gg, 256, SMEM_SZ>>>(5, b2 + 1024);

    k_out<<<tg, tb>>>(out);
}

// round 4
// speedup vs baseline: 1.0872x; 1.0872x over previous
#include <cuda_runtime.h>
#include <cuda_bf16.h>
#include <cstdint>
#include <cstddef>

#define DI __device__ __forceinline__

// ---------------- problem constants ----------------
constexpr int BATCH = 8, CH = 512, TT = 4096, PAD = 8, TP = TT + 2 * PAD;
constexpr int WELEM = CH * CH * 3;        // weights per conv
constexpr int WROW  = 3 * CH;             // 1536 (K per output row)
constexpr int TILE  = 128;                // M and N tile
constexpr int KC    = 64;                 // K chunk (bf16 elems, per tap)
constexpr int NCHK  = 8;                  // 512/64 ci chunks (taps fused inside)
constexpr int ROWS_B = 144;               // 128 tokens + shift margin (|shift|<=5, off=8)
// stage layout: A[3 taps][128][64] | Bhi[144][64] | Blo[144][64]
constexpr int A_OFF  = 0;                 // 49152 bytes
constexpr int BH_OFF = 49152;             // 18432 bytes
constexpr int BL_OFF = 67584;             // 18432 bytes
constexpr int STAGE  = 86016;
constexpr int SMEM_SZ = 2 * STAGE;        // 172032

// ---------------- static device scratch ----------------
__device__ __align__(256) float         g_r[(size_t)BATCH * TT * CH];
__device__ __align__(256) __nv_bfloat16 g_xhi[(size_t)BATCH * TP * CH];
__device__ __align__(256) __nv_bfloat16 g_xlo[(size_t)BATCH * TP * CH];
__device__ __align__(256) __nv_bfloat16 g_hhi[(size_t)BATCH * TP * CH];
__device__ __align__(256) __nv_bfloat16 g_hlo[(size_t)BATCH * TP * CH];
__device__ __align__(256) __nv_bfloat16 g_wq[6][(size_t)CH * WROW];
__device__ float  g_s[6];
__device__ double g_part[6 * 64];
__device__ float  g_a[3 * CH];
__device__ float  g_binv[3 * CH];

// ---------------- PTX helpers (sm_80-class only; no 'a' features) ----------------
DI uint32_t smem_u32(const void* p) {
    uint32_t a;
    asm("{ .reg .u64 t; cvta.to.shared.u64 t, %1; cvt.u32.u64 %0, t; }" : "=r"(a) : "l"(p));
    return a;
}
DI uint32_t swz(uint32_t o) { return o ^ ((o >> 3) & 0x70); }

DI void cp16(uint32_t dst, const void* src) {
    asm volatile("cp.async.cg.shared.global [%0], [%1], 16;" :: "r"(dst), "l"(src) : "memory");
}
DI void cp_commit() { asm volatile("cp.async.commit_group;" ::: "memory"); }
template <int N> DI void cp_wait() { asm volatile("cp.async.wait_group %0;" :: "n"(N) : "memory"); }

DI void ldm4(uint32_t* r, uint32_t addr) {
    asm volatile("ldmatrix.sync.aligned.m8n8.x4.shared.b16 {%0,%1,%2,%3}, [%4];"
                 : "=r"(r[0]), "=r"(r[1]), "=r"(r[2]), "=r"(r[3]) : "r"(addr));
}
DI void mma16816(float* c, const uint32_t* a, const uint32_t* b) {
    asm volatile(
        "mma.sync.aligned.m16n8k16.row.col.f32.bf16.bf16.f32 "
        "{%0,%1,%2,%3}, {%4,%5,%6,%7}, {%8,%9}, {%0,%1,%2,%3};"
        : "+f"(c[0]), "+f"(c[1]), "+f"(c[2]), "+f"(c[3])
        : "r"(a[0]), "r"(a[1]), "r"(a[2]), "r"(a[3]), "r"(b[0]), "r"(b[1]));
}

// ---------------- prep kernels ----------------
__global__ void k_wabs(const float* __restrict__ w1, const float* __restrict__ w2) {
    int conv = blockIdx.x >> 6, part = blockIdx.x & 63;
    const float* w = ((conv & 1) ? w2 : w1) + (size_t)(conv >> 1) * WELEM;
    int base = part * (WELEM / 64);
    double acc = 0.0;
    for (int i = threadIdx.x; i < WELEM / 64; i += 256) acc += (double)fabsf(w[base + i]);
    __shared__ double sm[256];
    sm[threadIdx.x] = acc;
    __syncthreads();
    for (int s = 128; s > 0; s >>= 1) {
        if (threadIdx.x < s) sm[threadIdx.x] += sm[threadIdx.x + s];
        __syncthreads();
    }
    if (threadIdx.x == 0) g_part[blockIdx.x] = sm[0];
}

__global__ void k_sfin() {
    __shared__ double sm[64];
    sm[threadIdx.x] = g_part[blockIdx.x * 64 + threadIdx.x];
    __syncthreads();
    for (int s = 32; s > 0; s >>= 1) {
        if (threadIdx.x < s) sm[threadIdx.x] += sm[threadIdx.x + s];
        __syncthreads();
    }
    if (threadIdx.x == 0) g_s[blockIdx.x] = (float)(sm[0] / (double)WELEM);
}

__global__ void k_quant(const float* __restrict__ w1, const float* __restrict__ w2) {
    size_t idx = (size_t)blockIdx.x * 256 + threadIdx.x;
    if (idx >= (size_t)6 * WELEM) return;
    int conv = (int)(idx / WELEM);
    int e = (int)(idx - (size_t)conv * WELEM);
    int co = e / WROW;
    int rem = e - co * WROW;
    int k = rem >> 9, ci = rem & 511;                 // dst layout [co][tap][ci]
    const float* w = ((conv & 1) ? w2 : w1) + (size_t)(conv >> 1) * WELEM;
    float s = g_s[conv] + 1e-5f;
    float q = rintf(w[(size_t)co * WROW + ci * 3 + k] / s); // src layout [co][ci][k]
    q = fminf(1.f, fmaxf(-1.f, q));
    g_wq[conv][e] = __float2bfloat16(q);
}

__global__ void k_act(const float* __restrict__ alpha, const float* __restrict__ beta) {
    int i = blockIdx.x * 256 + threadIdx.x;
    if (i >= 3 * CH) return;
    g_a[i] = expf(alpha[i]);
    g_binv[i] = 1.f / (expf(beta[i]) + 1e-9f);
}

__global__ void k_prep(const float* __restrict__ x) {
    __shared__ float tile[32][33];
    int b = blockIdx.z, c0 = blockIdx.y * 32, t0 = blockIdx.x * 32;
    int tx = threadIdx.x;
    for (int i = threadIdx.y; i < 32; i += 8)
        tile[i][tx] = x[((size_t)b * CH + c0 + i) * TT + t0 + tx];
    __syncthreads();
    for (int i = threadIdx.y; i < 32; i += 8) {
        float v = tile[tx][i];
        size_t ro = ((size_t)b * TT + t0 + i) * CH + c0 + tx;
        size_t po = ((size_t)b * TP + PAD + t0 + i) * CH + c0 + tx;
        g_r[ro] = v;
        __nv_bfloat16 hi = __float2bfloat16(v);
        g_xhi[po] = hi;
        g_xlo[po] = __float2bfloat16(v - __bfloat162float(hi));
    }
}

__global__ void k_out(float* __restrict__ out) {
    __shared__ float tile[32][33];
    int b = blockIdx.z, c0 = blockIdx.y * 32, t0 = blockIdx.x * 32;
    int tx = threadIdx.x;
    for (int i = threadIdx.y; i < 32; i += 8)
        tile[i][tx] = g_r[((size_t)b * TT + t0 + i) * CH + c0 + tx];
    __syncthreads();
    for (int i = threadIdx.y; i < 32; i += 8)
        out[((size_t)b * CH + c0 + i) * TT + t0 + tx] = tile[tx][i];
}

// ---------------- GEMM chunk loader (256 threads, 21 cp16/thread) ----------------
// Chunk c covers ci0 = c*64, all 3 taps of A, B rows [t0-8, t0+136) padded-space.
DI void load_chunk(int c, int tid, uint32_t sb, int m0, int b, int t0,
                   const __nv_bfloat16* __restrict__ Xhi,
                   const __nv_bfloat16* __restrict__ Xlo,
                   const __nv_bfloat16* __restrict__ W) {
    int buf = c & 1, ci0 = c * KC;
    uint32_t st = sb + buf * STAGE;
    const __nv_bfloat16* As = W + (size_t)m0 * WROW + ci0;
    size_t bbase = ((size_t)b * TP + t0) * CH + ci0;   // padded row t0 == token t0-8
#pragma unroll
    for (int jj = 0; jj < 12; jj++) {                  // A: 3*128*8 = 3072 cp16
        int idx = tid + 256 * jj;
        int tap = idx >> 10, e = idx & 1023;
        int row = e >> 3, c16 = e & 7;
        uint32_t so = swz((uint32_t)(row * 128 + c16 * 16));
        cp16(st + A_OFF + tap * 16384 + so,
             (const char*)(As + (size_t)row * WROW + tap * CH) + c16 * 16);
    }
#pragma unroll
    for (int jj = 0; jj < 9; jj++) {                   // B: 2*144*8 = 2304 cp16
        int idx = tid + 256 * jj;
        int plane = idx >= 1152;
        int e = idx - plane * 1152;
        int row = e >> 3, c16 = e & 7;
        uint32_t so = swz((uint32_t)(row * 128 + c16 * 16));
        const __nv_bfloat16* src = plane ? Xlo : Xhi;
        cp16(st + (plane ? BL_OFF : BH_OFF) + so,
             (const char*)(src + bbase + (size_t)row * CH) + c16 * 16);
    }
    cp_commit();
}

// ---------------- main GEMM kernel ----------------
// MODE 0: conv1 -> snake -> write g_h hi/lo
// MODE 1: conv2 -> residual update g_r, write g_x hi/lo for next block
// MODE 2: conv2 final -> residual update g_r only
template <int DIL, int MODE>
__global__ void __launch_bounds__(256, 1)
gemm_k(int conv, const float* __restrict__ bias) {
    extern __shared__ char smem[];
    uint32_t sb = smem_u32(smem);
    int tid = threadIdx.x;
    int wid = tid >> 5, lane = tid & 31;
    int wm = wid >> 2, wn = wid & 3;       // warp grid 2m x 4n (64x32 per warp)
    int m0 = blockIdx.x * TILE;
    int nt = blockIdx.y;
    int b = nt >> 5, t0 = (nt & 31) * TILE;
    const __nv_bfloat16* Xhi = (MODE == 0) ? g_xhi : g_hhi;
    const __nv_bfloat16* Xlo = (MODE == 0) ? g_xlo : g_hlo;
    const __nv_bfloat16* W = g_wq[conv];

    float acc[4][4][4];
#pragma unroll
    for (int i = 0; i < 4; i++)
#pragma unroll
        for (int j = 0; j < 4; j++)
#pragma unroll
            for (int r = 0; r < 4; r++) acc[i][j][r] = 0.f;

    // ldmatrix lane roles
    int lsel = lane >> 3, l7 = lane & 7;
    int a_row = (lsel & 1) * 8 + l7, a_kc = (lsel >> 1) * 8;   // A: m8 pair, k8 pair
    int b_row = (lsel >> 1) * 8 + l7, b_kc = (lsel & 1) * 8;   // B: n8 pair, k8 pair

    load_chunk(0, tid, sb, m0, b, t0, Xhi, Xlo, W);
#pragma unroll 1
    for (int c = 0; c < NCHK; c++) {
        if (c + 1 < NCHK) {
            load_chunk(c + 1, tid, sb, m0, b, t0, Xhi, Xlo, W);
            cp_wait<1>();
        } else {
            cp_wait<0>();
        }
        __syncthreads();
        uint32_t st = sb + (c & 1) * STAGE;
#pragma unroll
        for (int tap = 0; tap < 3; tap++) {
            uint32_t ab = st + A_OFF + tap * 16384;
            int rowoff = 8 + (tap - 1) * DIL;          // B smem row for token j is rowoff+j
#pragma unroll
            for (int ks = 0; ks < 4; ks++) {
                uint32_t afr[4][4];
#pragma unroll
                for (int mf = 0; mf < 4; mf++) {
                    uint32_t o = (uint32_t)((wm * 64 + mf * 16 + a_row) * 128 + (ks * 16 + a_kc) * 2);
                    ldm4(afr[mf], ab + swz(o));
                }
                uint32_t bh[4][2], bl[4][2];
#pragma unroll
                for (int h = 0; h < 2; h++) {
                    uint32_t o = (uint32_t)((rowoff + wn * 32 + h * 16 + b_row) * 128 +
                                            (ks * 16 + b_kc) * 2);
                    uint32_t r4[4];
                    ldm4(r4, st + BH_OFF + swz(o));
                    bh[2 * h][0] = r4[0]; bh[2 * h][1] = r4[1];
                    bh[2 * h + 1][0] = r4[2]; bh[2 * h + 1][1] = r4[3];
                    ldm4(r4, st + BL_OFF + swz(o));
                    bl[2 * h][0] = r4[0]; bl[2 * h][1] = r4[1];
                    bl[2 * h + 1][0] = r4[2]; bl[2 * h + 1][1] = r4[3];
                }
#pragma unroll
                for (int mf = 0; mf < 4; mf++)
#pragma unroll
                    for (int nf = 0; nf < 4; nf++) {
                        mma16816(acc[mf][nf], afr[mf], bh[nf]);
                        mma16816(acc[mf][nf], afr[mf], bl[nf]);
                    }
            }
        }
        __syncthreads();
    }

    // -------- epilogue --------
    const float s = g_s[conv];
    const int blkI = conv >> 1;
    int g = lane >> 2, tig = lane & 3;
    float biv[4][2], av[4][2], bvv[4][2];
#pragma unroll
    for (int mf = 0; mf < 4; mf++) {
        int co = m0 + wm * 64 + mf * 16 + g;
        biv[mf][0] = bias[co];
        biv[mf][1] = bias[co + 8];
        if (MODE == 0) {
            av[mf][0] = g_a[blkI * CH + co];
            av[mf][1] = g_a[blkI * CH + co + 8];
            bvv[mf][0] = g_binv[blkI * CH + co];
            bvv[mf][1] = g_binv[blkI * CH + co + 8];
        }
    }
#pragma unroll
    for (int mf = 0; mf < 4; mf++) {
        int co0 = m0 + wm * 64 + mf * 16 + g;
#pragma unroll
        for (int nf = 0; nf < 4; nf++) {
            int tb = t0 + wn * 32 + nf * 8 + 2 * tig;
#pragma unroll
            for (int r = 0; r < 4; r++) {
                int co = co0 + (r >> 1) * 8;
                int t = tb + (r & 1);
                float v = s * acc[mf][nf][r] + biv[mf][r >> 1];
                if (MODE == 0) {
                    float sn = __sinf(av[mf][r >> 1] * v);
                    v += bvv[mf][r >> 1] * sn * sn;
                    size_t o = ((size_t)b * TP + PAD + t) * CH + co;
                    __nv_bfloat16 hi = __float2bfloat16(v);
                    g_hhi[o] = hi;
                    g_hlo[o] = __float2bfloat16(v - __bfloat162float(hi));
                } else {
                    size_t ro = ((size_t)b * TT + t) * CH + co;
                    float rn = g_r[ro] + v;
                    g_r[ro] = rn;
                    if (MODE == 1) {
                        size_t o = ((size_t)b * TP + PAD + t) * CH + co;
                        __nv_bfloat16 hi = __float2bfloat16(rn);
                        g_xhi[o] = hi;
                        g_xlo[o] = __float2bfloat16(rn - __bfloat162float(hi));
                    }
                }
            }
        }
    }
}

// ---------------- launch ----------------
extern "C" void kernel_launch(void* const* d_in, const int* in_sizes, int n_in,
                              void* d_out, int out_size) {
    const float* x     = (const float*)d_in[0];
    const float* w1    = (const float*)d_in[1];
    const float* b1    = (const float*)d_in[2];
    const float* alpha = (const float*)d_in[3];
    const float* beta  = (const float*)d_in[4];
    const float* w2    = (const float*)d_in[5];
    const float* b2    = (const float*)d_in[6];
    float* out = (float*)d_out;

    cudaFuncSetAttribute(gemm_k<1, 0>, cudaFuncAttributeMaxDynamicSharedMemorySize, SMEM_SZ);
    cudaFuncSetAttribute(gemm_k<1, 1>, cudaFuncAttributeMaxDynamicSharedMemorySize, SMEM_SZ);
    cudaFuncSetAttribute(gemm_k<3, 0>, cudaFuncAttributeMaxDynamicSharedMemorySize, SMEM_SZ);
    cudaFuncSetAttribute(gemm_k<5, 0>, cudaFuncAttributeMaxDynamicSharedMemorySize, SMEM_SZ);
    cudaFuncSetAttribute(gemm_k<1, 2>, cudaFuncAttributeMaxDynamicSharedMemorySize, SMEM_SZ);

    k_wabs<<<6 * 64, 256>>>(w1, w2);
    k_sfin<<<6, 64>>>();
    k_quant<<<(int)(((size_t)6 * WELEM + 255) / 256), 256>>>(w1, w2);
    k_act<<<6, 256>>>(alpha, beta);

    dim3 tb(32, 8), tg(TT / 32, CH / 32, BATCH);
    k_prep<<<tg, tb>>>(x);

    dim3 gg(CH / TILE, BATCH * TT / TILE);   // (4, 256)
    gemm_k<1, 0><<<gg, 256, SMEM_SZ>>>(0, b1);
    gemm_k<1, 1><<<gg, 256, SMEM_SZ>>>(1, b2);
    gemm_k<3, 0><<<gg, 256, SMEM_SZ>>>(2, b1 + 512);
    gemm_k<1, 1><<<gg, 256, SMEM_SZ>>>(3, b2 + 512);
    gemm_k<5, 0><<<gg, 256, SMEM_SZ>>>(4, b1 + 1024);
    gemm_k<1, 2><<<gg, 256, SMEM_SZ>>>(5, b2 + 1024);

    k_out<<<tg, tb>>>(out);
}